// round 8
// baseline (speedup 1.0000x reference)
#include <cuda_runtime.h>
#include <cstdint>
#include <math.h>

// ============================================================================
// AttendAndSpell — single persistent kernel, 148 blocks x 256 threads.
// Fused: attention (2-pass smem-staged) + GEMM-LSTM epilogues + logits/sampler.
// ============================================================================

#define B_   128
#define R_   512
#define HID_ 512
#define VOC_ 64
#define T_   128
#define NB   148
#define NT   256
#define NTH  (NB * NT)
#define SMEM_DYN (64 * 512 * 4)   // 128KB chunk buffer / GEMM tiles

// ---------------- scratch ----------------
__device__ float g_hp  [(size_t)B_ * R_ * HID_];      // 134 MB
__device__ float g_phiT[512 * 512];
__device__ float g_psiT[512 * 512];
__device__ float g_WI0 [1024 * 2048];                 // gate-interleaved [k][d*4+g]
__device__ float g_WI1 [1024 * 2048];
__device__ float g_outT[512 * 64];
__device__ float g_ohI [64 * 2048];                   // one-hot rows, interleaved
__device__ float g_b0I [2048];                        // b_ih0+b_hh0 interleaved
__device__ float g_b1I [2048];
__device__ float g_sq  [B_ * 512];
__device__ float g_sq2 [B_ * 512];                    // K-split partial of sq
__device__ float g_XA  [B_ * 1024];                   // [c | s0]
__device__ float g_XB  [B_ * 1024];                   // [s0 | s1]
__device__ float g_S1  [B_ * 512];                    // fresh s1
__device__ float g_cs0 [B_ * 512];
__device__ float g_cs1 [B_ * 512];
__device__ int   g_z   [B_];
__device__ uint2 g_keys[T_];
__device__ unsigned g_bcnt = 0;
__device__ unsigned g_bgen = 0;

// ---------------- grid barrier (volatile poll, atomic arrive) ----------------
__device__ __forceinline__ void gbar() {
    __syncthreads();
    if (threadIdx.x == 0) {
        unsigned gen = *((volatile unsigned*)&g_bgen);
        __threadfence();
        if (atomicAdd(&g_bcnt, 1u) == NB - 1u) {
            atomicExch(&g_bcnt, 0u);
            __threadfence();
            atomicAdd(&g_bgen, 1u);
        } else {
            while (*((volatile unsigned*)&g_bgen) == gen) { __nanosleep(32); }
        }
        __threadfence();
    }
    __syncthreads();
}

// ---------------- Threefry-2x32 (bit-exact, proven) ----------------
__device__ __forceinline__ void tf2x32(uint32_t k0, uint32_t k1,
                                       uint32_t x0, uint32_t x1,
                                       uint32_t& o0, uint32_t& o1) {
    uint32_t k2 = k0 ^ k1 ^ 0x1BD11BDAu;
    x0 += k0; x1 += k1;
#define RR(r) { x0 += x1; x1 = (x1 << (r)) | (x1 >> (32 - (r))); x1 ^= x0; }
    RR(13) RR(15) RR(26) RR(6)   x0 += k1; x1 += k2 + 1u;
    RR(17) RR(29) RR(16) RR(24)  x0 += k2; x1 += k0 + 2u;
    RR(13) RR(15) RR(26) RR(6)   x0 += k0; x1 += k1 + 3u;
    RR(17) RR(29) RR(16) RR(24)  x0 += k1; x1 += k2 + 4u;
    RR(13) RR(15) RR(26) RR(6)   x0 += k2; x1 += k0 + 5u;
#undef RR
    o0 = x0; o1 = x1;
}

__device__ __forceinline__ float bits_to_unit(uint32_t bits) {
    return __uint_as_float((bits >> 9) | 0x3f800000u) - 1.0f;
}

__device__ __forceinline__ float sigm(float x) { return 1.f / (1.f + expf(-x)); }

// ---------------- setup ----------------
__device__ void phase_setup(const float* __restrict__ phi_w, const float* __restrict__ psi_w,
                            const float* __restrict__ w_ih0, const float* __restrict__ w_hh0,
                            const float* __restrict__ b_ih0, const float* __restrict__ b_hh0,
                            const float* __restrict__ w_ih1, const float* __restrict__ w_hh1,
                            const float* __restrict__ b_ih1, const float* __restrict__ b_hh1,
                            const float* __restrict__ out_w, const int* __restrict__ y) {
    int gt = blockIdx.x * NT + threadIdx.x;
    for (int i = gt; i < 512 * 512; i += NTH) {
        int k = i >> 9, j = i & 511;
        g_phiT[i] = phi_w[j * 512 + k];
        g_psiT[i] = psi_w[j * 512 + k];
    }
    for (int i = gt; i < 1024 * 2048; i += NTH) {
        int k = i >> 11, col = i & 2047, d = col >> 2, g = col & 3;
        int oc = g * 512 + d;
        g_WI0[i] = (k < 512) ? w_ih0[oc * 576 + 64 + k] : w_hh0[oc * 512 + (k - 512)];
        g_WI1[i] = (k < 512) ? w_ih1[oc * 512 + k]      : w_hh1[oc * 512 + (k - 512)];
    }
    for (int i = gt; i < 64 * 2048; i += NTH) {
        int v = i >> 11, col = i & 2047, d = col >> 2, g = col & 3;
        g_ohI[i] = w_ih0[(g * 512 + d) * 576 + v];
    }
    for (int i = gt; i < 2048; i += NTH) {
        int d = i >> 2, g = i & 3;
        g_b0I[i] = b_ih0[g * 512 + d] + b_hh0[g * 512 + d];
        g_b1I[i] = b_ih1[g * 512 + d] + b_hh1[g * 512 + d];
    }
    for (int i = gt; i < 512 * 64; i += NTH) {
        int k = i >> 6, v = i & 63;
        g_outT[i] = out_w[v * 512 + k];
    }
    for (int i = gt; i < B_ * 1024; i += NTH) { g_XA[i] = 0.f; g_XB[i] = 0.f; }
    for (int i = gt; i < B_ * 512; i += NTH) { g_cs0[i] = 0.f; g_cs1[i] = 0.f; g_S1[i] = 0.f; }
    if (gt < T_) {
        uint32_t a, b;
        tf2x32(0u, 42u, 0u, (uint32_t)gt, a, b);
        g_keys[gt] = make_uint2(a, b);
    }
    if (gt < B_) g_z[gt] = y[gt * (T_ + 1)];
}

// ---------------- 64x64 fp32 GEMM (hp precompute) ----------------
__device__ void gemm64(float* sbuf, const float* __restrict__ A,
                       const float* __restrict__ Bm, float* __restrict__ C,
                       const float* __restrict__ bias) {
    float (*As)[68] = (float(*)[68])sbuf;
    float (*Bs)[64] = (float(*)[64])(sbuf + 16 * 68);
    int tid = threadIdx.x;
    int r   = tid >> 2, kc = (tid & 3) << 2;
    int bkk = tid >> 4, bnc = (tid & 15) << 2;
    int tx  = tid & 15, ty = tid >> 4;
    for (int tile = blockIdx.x; tile < 1024 * 8; tile += NB) {
        int m0 = (tile >> 3) << 6;
        int n0 = (tile & 7) << 6;
        float acc[16];
#pragma unroll
        for (int i = 0; i < 16; i++) acc[i] = 0.f;
        const float* Ap = A + (size_t)(m0 + r) * 512 + kc;
        const float* Bp = Bm + (size_t)bkk * 512 + n0 + bnc;
        for (int k0 = 0; k0 < 512; k0 += 16) {
            float4 av = *(const float4*)(Ap + k0);
            float4 bv = *(const float4*)(Bp + (size_t)k0 * 512);
            __syncthreads();
            As[kc][r] = av.x; As[kc + 1][r] = av.y;
            As[kc + 2][r] = av.z; As[kc + 3][r] = av.w;
            *(float4*)&Bs[bkk][bnc] = bv;
            __syncthreads();
#pragma unroll
            for (int kk = 0; kk < 16; kk++) {
                float4 a4 = *(const float4*)&As[kk][ty << 2];
                float4 b4 = *(const float4*)&Bs[kk][tx << 2];
                acc[0]  = fmaf(a4.x, b4.x, acc[0]);  acc[1]  = fmaf(a4.x, b4.y, acc[1]);
                acc[2]  = fmaf(a4.x, b4.z, acc[2]);  acc[3]  = fmaf(a4.x, b4.w, acc[3]);
                acc[4]  = fmaf(a4.y, b4.x, acc[4]);  acc[5]  = fmaf(a4.y, b4.y, acc[5]);
                acc[6]  = fmaf(a4.y, b4.z, acc[6]);  acc[7]  = fmaf(a4.y, b4.w, acc[7]);
                acc[8]  = fmaf(a4.z, b4.x, acc[8]);  acc[9]  = fmaf(a4.z, b4.y, acc[9]);
                acc[10] = fmaf(a4.z, b4.z, acc[10]); acc[11] = fmaf(a4.z, b4.w, acc[11]);
                acc[12] = fmaf(a4.w, b4.x, acc[12]); acc[13] = fmaf(a4.w, b4.y, acc[13]);
                acc[14] = fmaf(a4.w, b4.z, acc[14]); acc[15] = fmaf(a4.w, b4.w, acc[15]);
            }
        }
        float4 bb = *(const float4*)&bias[n0 + (tx << 2)];
#pragma unroll
        for (int i = 0; i < 4; i++) {
            float4 rr;
            rr.x = acc[i * 4 + 0] + bb.x; rr.y = acc[i * 4 + 1] + bb.y;
            rr.z = acc[i * 4 + 2] + bb.z; rr.w = acc[i * 4 + 3] + bb.w;
            *(float4*)&C[(size_t)(m0 + (ty << 2) + i) * 512 + n0 + (tx << 2)] = rr;
        }
    }
}

// ---------------- fused GEMM (128x2048, K=1024) + LSTM cell epilogue --------
__device__ void gemm_lstm(float* sbuf, const float* __restrict__ A,
                          const float* __restrict__ WI, const float* __restrict__ bI,
                          float* __restrict__ cs, float* __restrict__ outp,
                          int out_ld, int layer0) {
    float (*As)[34] = (float(*)[34])sbuf;
    float (*Bs)[64] = (float(*)[64])(sbuf + 16 * 34);
    int tile = blockIdx.x;                      // < 128
    int tid = threadIdx.x;
    int tx = tid & 15, ty = tid >> 4;
    int m0 = (tile >> 5) << 5;                  // 4 m-tiles of 32
    int n0 = (tile & 31) << 6;                  // 32 n-tiles of 64
    int ar = tid >> 3, akc = (tid & 7) << 1;
    int br = tid >> 4, bc = (tid & 15) << 2;
    float acc[2][4] = {{0.f,0.f,0.f,0.f},{0.f,0.f,0.f,0.f}};
    const float* Ap = A + (size_t)(m0 + ar) * 1024 + akc;
    const float* Bp = WI + (size_t)br * 2048 + n0 + bc;
    for (int k0 = 0; k0 < 1024; k0 += 16) {
        float2 av = *(const float2*)(Ap + k0);
        float4 bv = *(const float4*)(Bp + (size_t)k0 * 2048);
        __syncthreads();
        As[akc][ar] = av.x; As[akc + 1][ar] = av.y;
        *(float4*)&Bs[br][bc] = bv;
        __syncthreads();
#pragma unroll
        for (int kk = 0; kk < 16; kk++) {
            float a0 = As[kk][ty * 2];
            float a1 = As[kk][ty * 2 + 1];
            float4 b = *(const float4*)&Bs[kk][tx << 2];
            acc[0][0] = fmaf(a0, b.x, acc[0][0]); acc[0][1] = fmaf(a0, b.y, acc[0][1]);
            acc[0][2] = fmaf(a0, b.z, acc[0][2]); acc[0][3] = fmaf(a0, b.w, acc[0][3]);
            acc[1][0] = fmaf(a1, b.x, acc[1][0]); acc[1][1] = fmaf(a1, b.y, acc[1][1]);
            acc[1][2] = fmaf(a1, b.z, acc[1][2]); acc[1][3] = fmaf(a1, b.w, acc[1][3]);
        }
    }
    int d = (n0 >> 2) + tx;
    float4 bb = *(const float4*)&bI[n0 + (tx << 2)];
#pragma unroll
    for (int i = 0; i < 2; i++) {
        int b = m0 + ty * 2 + i;
        float gi = acc[i][0] + bb.x;
        float gf = acc[i][1] + bb.y;
        float gg = acc[i][2] + bb.z;
        float go = acc[i][3] + bb.w;
        if (layer0) {
            const float4 oh = *(const float4*)&g_ohI[(size_t)g_z[b] * 2048 + n0 + (tx << 2)];
            gi += oh.x; gf += oh.y; gg += oh.z; go += oh.w;
        }
        float ii = sigm(gi), ff = sigm(gf), g2 = tanhf(gg), oo = sigm(go);
        float c = ff * cs[b * 512 + d] + ii * g2;
        cs[b * 512 + d] = c;
        outp[b * out_ld + d] = oo * tanhf(c);
    }
}

// ---------------- attention: block per b, 8 chunks of 64 rows ----------------
__device__ void attn_block(float* sbuf) {
    __shared__ float e_s[64], p_s[64];
    __shared__ float cfin[2][512];
    __shared__ float sS[2];
    int b = blockIdx.x;
    int tid = threadIdx.x, lane = tid & 31, w = tid >> 5;
    int grp = w >> 2, gl = ((w & 3) << 5) + lane;     // group row-half, lane's d/4
    const float* sqb  = g_sq  + b * 512;
    const float* sqb2 = g_sq2 + b * 512;
    float4 qf[4];
#pragma unroll
    for (int j = 0; j < 4; j++) {
        float4 a = *(const float4*)(sqb  + j * 128 + lane * 4);
        float4 c = *(const float4*)(sqb2 + j * 128 + lane * 4);
        qf[j] = make_float4(a.x + c.x, a.y + c.y, a.z + c.z, a.w + c.w);
    }
    float4 cacc = make_float4(0.f, 0.f, 0.f, 0.f);
    float Mrun = -INFINITY, Srun = 0.f;
    const float* hpb = g_hp + (size_t)b * (R_ * HID_);
    for (int ch = 0; ch < 8; ch++) {
        const float* base = hpb + (size_t)ch * 64 * 512;
        // ---- pass A: scores + smem staging (deep-MLP batched loads) ----
#pragma unroll
        for (int bt = 0; bt < 2; bt++) {
            int r0 = w * 8 + bt * 4;
            float4 v[4][4];
#pragma unroll
            for (int i = 0; i < 4; i++)
#pragma unroll
                for (int j = 0; j < 4; j++)
                    v[i][j] = *(const float4*)(base + (r0 + i) * 512 + j * 128 + lane * 4);
#pragma unroll
            for (int i = 0; i < 4; i++)
#pragma unroll
                for (int j = 0; j < 4; j++)
                    *(float4*)&sbuf[(r0 + i) * 512 + j * 128 + lane * 4] = v[i][j];
            float dt[4];
#pragma unroll
            for (int i = 0; i < 4; i++) {
                float dd = 0.f;
#pragma unroll
                for (int j = 0; j < 4; j++) {
                    dd = fmaf(qf[j].x, v[i][j].x, dd);
                    dd = fmaf(qf[j].y, v[i][j].y, dd);
                    dd = fmaf(qf[j].z, v[i][j].z, dd);
                    dd = fmaf(qf[j].w, v[i][j].w, dd);
                }
                dt[i] = dd;
            }
#pragma unroll
            for (int off = 16; off > 0; off >>= 1) {
#pragma unroll
                for (int i = 0; i < 4; i++)
                    dt[i] += __shfl_xor_sync(0xffffffffu, dt[i], off);
            }
            if (lane == 0) {
                e_s[r0] = dt[0]; e_s[r0 + 1] = dt[1];
                e_s[r0 + 2] = dt[2]; e_s[r0 + 3] = dt[3];
            }
        }
        __syncthreads();
        // ---- chunk softmax update (redundant per thread, no extra sync) ----
        float Mc = -INFINITY;
#pragma unroll
        for (int r = 0; r < 64; r++) Mc = fmaxf(Mc, e_s[r]);
        float Mnew = fmaxf(Mrun, Mc);
        float corr = expf(Mrun - Mnew);
        cacc.x *= corr; cacc.y *= corr; cacc.z *= corr; cacc.w *= corr;
        Srun *= corr;
        if (tid < 64) p_s[tid] = expf(e_s[tid] - Mnew);
        Mrun = Mnew;
        __syncthreads();
        // ---- pass B: value accumulation from smem (reduction-free) ----
        const float* sb = sbuf + grp * 32 * 512 + gl * 4;
        const float* pp = p_s + grp * 32;
#pragma unroll 8
        for (int rr = 0; rr < 32; rr++) {
            float pv = pp[rr];
            float4 hv = *(const float4*)(sb + rr * 512);
            cacc.x = fmaf(pv, hv.x, cacc.x);
            cacc.y = fmaf(pv, hv.y, cacc.y);
            cacc.z = fmaf(pv, hv.z, cacc.z);
            cacc.w = fmaf(pv, hv.w, cacc.w);
            Srun += pv;
        }
        __syncthreads();
    }
    *(float4*)&cfin[grp][gl * 4] = cacc;
    if ((w & 3) == 0 && lane == 0) sS[grp] = Srun;
    __syncthreads();
    float inv = 1.f / (sS[0] + sS[1]);
    for (int i = tid; i < 512; i += NT)
        g_XA[b * 1024 + i] = (cfin[0][i] + cfin[1][i]) * inv;
}

// ---------------- sq GEMM tile (K-split: 64 tiles) ----------------
__device__ void sq_tile(float* sbuf, int tile, const float* __restrict__ phi_b) {
    float (*As)[34] = (float(*)[34])sbuf;
    float (*Bs)[64] = (float(*)[64])(sbuf + 16 * 34);
    int kh = tile >> 5, r = tile & 31;
    int m0 = (r >> 3) << 5, n0 = (r & 7) << 6;
    const float* A  = g_S1 + kh * 256;
    const float* Bm = g_phiT + kh * 256 * 512;
    float* C = kh ? g_sq2 : g_sq;
    int tid = threadIdx.x;
    int tx = tid & 15, ty = tid >> 4;
    int ar = tid >> 3, akc = (tid & 7) << 1;
    int br = tid >> 4, bc = (tid & 15) << 2;
    float acc[2][4] = {{0.f,0.f,0.f,0.f},{0.f,0.f,0.f,0.f}};
    const float* Ap = A + (m0 + ar) * 512 + akc;
    const float* Bp = Bm + br * 512 + n0 + bc;
    for (int k0 = 0; k0 < 256; k0 += 16) {
        float2 av = *(const float2*)(Ap + k0);
        float4 bv = *(const float4*)(Bp + k0 * 512);
        __syncthreads();
        As[akc][ar] = av.x; As[akc + 1][ar] = av.y;
        *(float4*)&Bs[br][bc] = bv;
        __syncthreads();
#pragma unroll
        for (int kk = 0; kk < 16; kk++) {
            float a0 = As[kk][ty * 2];
            float a1 = As[kk][ty * 2 + 1];
            float4 bq = *(const float4*)&Bs[kk][tx << 2];
            acc[0][0] = fmaf(a0, bq.x, acc[0][0]); acc[0][1] = fmaf(a0, bq.y, acc[0][1]);
            acc[0][2] = fmaf(a0, bq.z, acc[0][2]); acc[0][3] = fmaf(a0, bq.w, acc[0][3]);
            acc[1][0] = fmaf(a1, bq.x, acc[1][0]); acc[1][1] = fmaf(a1, bq.y, acc[1][1]);
            acc[1][2] = fmaf(a1, bq.z, acc[1][2]); acc[1][3] = fmaf(a1, bq.w, acc[1][3]);
        }
    }
    float4 bb = make_float4(0.f, 0.f, 0.f, 0.f);
    if (!kh) bb = *(const float4*)&phi_b[n0 + (tx << 2)];
#pragma unroll
    for (int i = 0; i < 2; i++) {
        float4 rr;
        rr.x = acc[i][0] + bb.x; rr.y = acc[i][1] + bb.y;
        rr.z = acc[i][2] + bb.z; rr.w = acc[i][3] + bb.w;
        *(float4*)&C[(m0 + ty * 2 + i) * 512 + n0 + (tx << 2)] = rr;
    }
}

// ---------------- logits + sampler (bit-exact threefry path) ----------------
__device__ void logits_sample(int t, const float* __restrict__ out_b,
                              const int* __restrict__ y, float* __restrict__ out) {
    __shared__ float sl[4][64];
    __shared__ float sg2[64];
    int b = blockIdx.x;
    if (b < B_) {
        int tid = threadIdx.x, v = tid & 63, part = tid >> 6;
        const float* s1 = g_S1 + b * 512 + part * 128;
        const float* ot = g_outT + part * 128 * 64 + v;
        float a0 = 0.f, a1 = 0.f;
#pragma unroll 4
        for (int k = 0; k < 128; k += 2) {
            a0 = fmaf(s1[k],     ot[k * 64],       a0);
            a1 = fmaf(s1[k + 1], ot[(k + 1) * 64], a1);
        }
        sl[part][v] = a0 + a1;
        __syncthreads();
        uint2 kt = g_keys[t];
        uint32_t k1a, k1b;
        tf2x32(kt.x, kt.y, 0u, 0u, k1a, k1b);
        if (tid < 64) {
            float logit = sl[0][tid] + sl[1][tid] + sl[2][tid] + sl[3][tid] + out_b[tid];
            out[((size_t)b * T_ + t) * VOC_ + tid] = logit;
            uint32_t r0, r1;
            tf2x32(k1a, k1b, 0u, (uint32_t)(b * VOC_ + tid), r0, r1);
            float f = bits_to_unit(r0 ^ r1);
            float u2 = fmaxf(f, 1.17549435e-38f);
            sg2[tid] = logit + (-logf(-logf(u2)));
        }
        __syncthreads();
        if (tid < 32) {
            float v0 = sg2[tid], v1 = sg2[tid + 32];
            int i0 = tid;
            if (v1 > v0) { v0 = v1; i0 = tid + 32; }
#pragma unroll
            for (int off = 16; off > 0; off >>= 1) {
                float ov = __shfl_down_sync(0xffffffffu, v0, off);
                int   oi = __shfl_down_sync(0xffffffffu, i0, off);
                if (ov > v0 || (ov == v0 && oi < i0)) { v0 = ov; i0 = oi; }
            }
            if (tid == 0) {
                uint32_t k2a, k2b, r0, r1;
                tf2x32(kt.x, kt.y, 0u, 1u, k2a, k2b);
                tf2x32(k2a, k2b, 0u, (uint32_t)b, r0, r1);
                float f = fmaxf(bits_to_unit(r0 ^ r1), 0.0f);
                g_z[b] = (f < 0.1f) ? i0 : y[b * (T_ + 1) + t + 1];
            }
        }
        __syncthreads();
    }
}

// ============================================================================
__global__ void __launch_bounds__(NT)
aas_persistent(const float* __restrict__ h,
               const float* __restrict__ phi_w, const float* __restrict__ phi_b,
               const float* __restrict__ psi_w, const float* __restrict__ psi_b,
               const float* __restrict__ w_ih0, const float* __restrict__ w_hh0,
               const float* __restrict__ b_ih0, const float* __restrict__ b_hh0,
               const float* __restrict__ w_ih1, const float* __restrict__ w_hh1,
               const float* __restrict__ b_ih1, const float* __restrict__ b_hh1,
               const float* __restrict__ out_w, const float* __restrict__ out_b,
               const int* __restrict__ y, float* __restrict__ out) {
    extern __shared__ float sbuf[];
    phase_setup(phi_w, psi_w, w_ih0, w_hh0, b_ih0, b_hh0,
                w_ih1, w_hh1, b_ih1, b_hh1, out_w, y);
    gbar();
    gemm64(sbuf, h, g_psiT, g_hp, psi_b);              // hp = h @ psi^T + psi_b
    gbar();
    if (blockIdx.x >= 84) sq_tile(sbuf, blockIdx.x - 84, phi_b);  // initial sq
    gbar();

    for (int t = 0; t < T_; t++) {
        // ---- phase 1: attention (c -> XA[:, :512]); idles copy S1 -> XB s1 half
        if (blockIdx.x < B_) attn_block(sbuf);
        else {
            for (int i = (blockIdx.x - 128) * NT + threadIdx.x; i < B_ * 512; i += 20 * NT) {
                int b = i >> 9, d = i & 511;
                g_XB[b * 1024 + 512 + d] = g_S1[i];
            }
        }
        gbar();
        // ---- phase 2: gates0 GEMM + LSTM0 cell -> s0 into XB[:, :512]
        if (blockIdx.x < B_)
            gemm_lstm(sbuf, g_XA, g_WI0, g_b0I, g_cs0, g_XB, 1024, 1);
        gbar();
        // ---- phase 3: gates1 GEMM + LSTM1 cell -> s1 into S1; idles copy s0 -> XA
        if (blockIdx.x < B_)
            gemm_lstm(sbuf, g_XB, g_WI1, g_b1I, g_cs1, g_S1, 512, 0);
        else {
            for (int i = (blockIdx.x - 128) * NT + threadIdx.x; i < B_ * 512; i += 20 * NT) {
                int b = i >> 9, d = i & 511;
                g_XA[b * 1024 + 512 + d] = g_XB[b * 1024 + d];
            }
        }
        gbar();
        // ---- phase 4: logits + sampler (blocks<128) and next-step sq (blocks 84..147)
        logits_sample(t, out_b, y, out);
        if (blockIdx.x >= 84) sq_tile(sbuf, blockIdx.x - 84, phi_b);
        gbar();
    }
}

extern "C" void kernel_launch(void* const* d_in, const int* in_sizes, int n_in,
                              void* d_out, int out_size) {
    const float* h     = (const float*)d_in[0];
    const float* phi_w = (const float*)d_in[1];
    const float* phi_b = (const float*)d_in[2];
    const float* psi_w = (const float*)d_in[3];
    const float* psi_b = (const float*)d_in[4];
    const float* w_ih0 = (const float*)d_in[5];
    const float* w_hh0 = (const float*)d_in[6];
    const float* b_ih0 = (const float*)d_in[7];
    const float* b_hh0 = (const float*)d_in[8];
    const float* w_ih1 = (const float*)d_in[9];
    const float* w_hh1 = (const float*)d_in[10];
    const float* b_ih1 = (const float*)d_in[11];
    const float* b_hh1 = (const float*)d_in[12];
    const float* out_w = (const float*)d_in[13];
    const float* out_b = (const float*)d_in[14];
    const int*   y     = (const int*)d_in[15];
    float* out = (float*)d_out;

    cudaFuncSetAttribute(aas_persistent,
                         cudaFuncAttributeMaxDynamicSharedMemorySize, SMEM_DYN);
    aas_persistent<<<NB, NT, SMEM_DYN>>>(h, phi_w, phi_b, psi_w, psi_b,
                                         w_ih0, w_hh0, b_ih0, b_hh0,
                                         w_ih1, w_hh1, b_ih1, b_hh1,
                                         out_w, out_b, y, out);
}

// round 9
// speedup vs baseline: 1.3533x; 1.3533x over previous
#include <cuda_runtime.h>
#include <cstdint>
#include <math.h>

// ============================================================================
// AttendAndSpell — persistent kernel, 148 x 256.
// Gate weights resident in SMEM; register-pipelined attention; ping-pong state.
// ============================================================================

#define B_   128
#define R_   512
#define HID_ 512
#define VOC_ 64
#define T_   128
#define NB   148
#define NT   256
#define NTH  (NB * NT)
// dyn smem: gates blocks: WI0s(64KB) WI1s(64KB) Astage(16KB); sq blocks: phis(64KB) Astage(16KB)
#define SMEM_DYN (36864 * 4)

// ---------------- scratch ----------------
__device__ float g_hp  [(size_t)B_ * R_ * HID_];      // 134 MB
__device__ float g_psiT[512 * 512];
__device__ float g_outT[512 * 64];
__device__ float g_ohI [64 * 2048];                   // one-hot rows, gate-interleaved
__device__ float g_b0I [2048];
__device__ float g_b1I [2048];
__device__ float g_sq  [B_ * 512];
__device__ float g_XA  [2][B_ * 1024];                // [c | s0], ping-pong by t
__device__ float g_XB  [2][B_ * 1024];                // [s0 | s1], ping-pong by t
__device__ float g_S1  [B_ * 512];
__device__ float g_cs0 [B_ * 512];
__device__ float g_cs1 [B_ * 512];
__device__ int   g_z   [B_];
__device__ uint2 g_keys[T_];
__device__ unsigned g_bcnt = 0;
__device__ unsigned g_bgen = 0;

// ---------------- grid barrier (proven R7/R8 pattern) ----------------
__device__ __forceinline__ void gbar() {
    __syncthreads();
    if (threadIdx.x == 0) {
        unsigned gen = *((volatile unsigned*)&g_bgen);
        __threadfence();
        if (atomicAdd(&g_bcnt, 1u) == NB - 1u) {
            atomicExch(&g_bcnt, 0u);
            __threadfence();
            atomicAdd(&g_bgen, 1u);
        } else {
            while (*((volatile unsigned*)&g_bgen) == gen) { __nanosleep(32); }
        }
        __threadfence();
    }
    __syncthreads();
}

// ---------------- Threefry-2x32 (bit-exact, proven) ----------------
__device__ __forceinline__ void tf2x32(uint32_t k0, uint32_t k1,
                                       uint32_t x0, uint32_t x1,
                                       uint32_t& o0, uint32_t& o1) {
    uint32_t k2 = k0 ^ k1 ^ 0x1BD11BDAu;
    x0 += k0; x1 += k1;
#define RR(r) { x0 += x1; x1 = (x1 << (r)) | (x1 >> (32 - (r))); x1 ^= x0; }
    RR(13) RR(15) RR(26) RR(6)   x0 += k1; x1 += k2 + 1u;
    RR(17) RR(29) RR(16) RR(24)  x0 += k2; x1 += k0 + 2u;
    RR(13) RR(15) RR(26) RR(6)   x0 += k0; x1 += k1 + 3u;
    RR(17) RR(29) RR(16) RR(24)  x0 += k1; x1 += k2 + 4u;
    RR(13) RR(15) RR(26) RR(6)   x0 += k2; x1 += k0 + 5u;
#undef RR
    o0 = x0; o1 = x1;
}

__device__ __forceinline__ float bits_to_unit(uint32_t bits) {
    return __uint_as_float((bits >> 9) | 0x3f800000u) - 1.0f;
}

__device__ __forceinline__ float sigm(float x) { return 1.f / (1.f + expf(-x)); }

// ---------------- setup ----------------
__device__ void phase_setup(const float* __restrict__ psi_w,
                            const float* __restrict__ phi_b,
                            const float* __restrict__ w_ih0,
                            const float* __restrict__ b_ih0, const float* __restrict__ b_hh0,
                            const float* __restrict__ b_ih1, const float* __restrict__ b_hh1,
                            const float* __restrict__ out_w, const int* __restrict__ y) {
    int gt = blockIdx.x * NT + threadIdx.x;
    for (int i = gt; i < 512 * 512; i += NTH) {
        int k = i >> 9, j = i & 511;
        g_psiT[i] = psi_w[j * 512 + k];
    }
    for (int i = gt; i < 64 * 2048; i += NTH) {
        int v = i >> 11, col = i & 2047, d = col >> 2, g = col & 3;
        g_ohI[i] = w_ih0[(g * 512 + d) * 576 + v];
    }
    for (int i = gt; i < 2048; i += NTH) {
        int d = i >> 2, g = i & 3;
        g_b0I[i] = b_ih0[g * 512 + d] + b_hh0[g * 512 + d];
        g_b1I[i] = b_ih1[g * 512 + d] + b_hh1[g * 512 + d];
    }
    for (int i = gt; i < 512 * 64; i += NTH) {
        int k = i >> 6, v = i & 63;
        g_outT[i] = out_w[v * 512 + k];
    }
    for (int i = gt; i < B_ * 1024; i += NTH) {
        g_XA[0][i] = 0.f; g_XA[1][i] = 0.f;
        g_XB[0][i] = 0.f; g_XB[1][i] = 0.f;
    }
    for (int i = gt; i < B_ * 512; i += NTH) {
        g_cs0[i] = 0.f; g_cs1[i] = 0.f; g_S1[i] = 0.f;
        g_sq[i] = phi_b[i & 511];               // s1=0 -> sq = phi_b
    }
    if (gt < T_) {
        uint32_t a, b;
        tf2x32(0u, 42u, 0u, (uint32_t)gt, a, b);
        g_keys[gt] = make_uint2(a, b);
    }
    if (gt < B_) g_z[gt] = y[gt * (T_ + 1)];
}

// ---------------- hp precompute: 64x64 tiles, prefetch ----------------
__device__ void gemm64(float* sbuf, const float* __restrict__ A,
                       const float* __restrict__ Bm, float* __restrict__ C,
                       const float* __restrict__ bias) {
    float (*As)[68] = (float(*)[68])sbuf;
    float (*Bs)[64] = (float(*)[64])(sbuf + 16 * 68);
    int tid = threadIdx.x;
    int r   = tid >> 2, kc = (tid & 3) << 2;
    int bkk = tid >> 4, bnc = (tid & 15) << 2;
    int tx  = tid & 15, ty = tid >> 4;
    for (int tile = blockIdx.x; tile < 1024 * 8; tile += NB) {
        int m0 = (tile >> 3) << 6;
        int n0 = (tile & 7) << 6;
        float acc[16];
#pragma unroll
        for (int i = 0; i < 16; i++) acc[i] = 0.f;
        const float* Ap = A + (size_t)(m0 + r) * 512 + kc;
        const float* Bp = Bm + (size_t)bkk * 512 + n0 + bnc;
        float4 av = *(const float4*)(Ap);
        float4 bv = *(const float4*)(Bp);
        for (int k0 = 0; k0 < 512; k0 += 16) {
            __syncthreads();
            As[kc][r] = av.x; As[kc + 1][r] = av.y;
            As[kc + 2][r] = av.z; As[kc + 3][r] = av.w;
            *(float4*)&Bs[bkk][bnc] = bv;
            __syncthreads();
            if (k0 + 16 < 512) {
                av = *(const float4*)(Ap + k0 + 16);
                bv = *(const float4*)(Bp + (size_t)(k0 + 16) * 512);
            }
#pragma unroll
            for (int kk = 0; kk < 16; kk++) {
                float4 a4 = *(const float4*)&As[kk][ty << 2];
                float4 b4 = *(const float4*)&Bs[kk][tx << 2];
                acc[0]  = fmaf(a4.x, b4.x, acc[0]);  acc[1]  = fmaf(a4.x, b4.y, acc[1]);
                acc[2]  = fmaf(a4.x, b4.z, acc[2]);  acc[3]  = fmaf(a4.x, b4.w, acc[3]);
                acc[4]  = fmaf(a4.y, b4.x, acc[4]);  acc[5]  = fmaf(a4.y, b4.y, acc[5]);
                acc[6]  = fmaf(a4.y, b4.z, acc[6]);  acc[7]  = fmaf(a4.y, b4.w, acc[7]);
                acc[8]  = fmaf(a4.z, b4.x, acc[8]);  acc[9]  = fmaf(a4.z, b4.y, acc[9]);
                acc[10] = fmaf(a4.z, b4.z, acc[10]); acc[11] = fmaf(a4.z, b4.w, acc[11]);
                acc[12] = fmaf(a4.w, b4.x, acc[12]); acc[13] = fmaf(a4.w, b4.y, acc[13]);
                acc[14] = fmaf(a4.w, b4.z, acc[14]); acc[15] = fmaf(a4.w, b4.w, acc[15]);
            }
        }
        float4 bb = *(const float4*)&bias[n0 + (tx << 2)];
#pragma unroll
        for (int i = 0; i < 4; i++) {
            float4 rr;
            rr.x = acc[i * 4 + 0] + bb.x; rr.y = acc[i * 4 + 1] + bb.y;
            rr.z = acc[i * 4 + 2] + bb.z; rr.w = acc[i * 4 + 3] + bb.w;
            *(float4*)&C[(size_t)(m0 + (ty << 2) + i) * 512 + n0 + (tx << 2)] = rr;
        }
    }
}

// ---------------- A-stage store helper ----------------
__device__ __forceinline__ void stage_store(float* As, int buf, float4 pa, float4 pb,
                                            int srow, int skoff) {
    float* d = As + buf * 2048;
    d[(skoff + 0) * 128 + srow] = pa.x; d[(skoff + 1) * 128 + srow] = pa.y;
    d[(skoff + 2) * 128 + srow] = pa.z; d[(skoff + 3) * 128 + srow] = pa.w;
    d[(skoff + 4) * 128 + srow] = pb.x; d[(skoff + 5) * 128 + srow] = pb.y;
    d[(skoff + 6) * 128 + srow] = pb.z; d[(skoff + 7) * 128 + srow] = pb.w;
}

// ---------------- gates GEMM (128 x 16 cols, K=1024) + LSTM epilogue --------
// B resident in smem WIs[1024][16]. A staged via double-buffered smem.
__device__ void gemm_gates(const float* __restrict__ A, const float* __restrict__ WIs,
                           float* As, const float* __restrict__ bI,
                           float* __restrict__ cs,
                           float* __restrict__ o1, int ld1,
                           float* __restrict__ o2, int ld2,
                           int n0, int layer0) {
    int tid = threadIdx.x;
    int ty = tid >> 2;                  // 0..63
    int tx = tid & 3;                   // 0..3  (d within tile)
    int b0r = ty, b1r = ty + 64;
    int srow = tid >> 1, skoff = (tid & 1) << 3;
    float acc0[4] = {0.f,0.f,0.f,0.f}, acc1[4] = {0.f,0.f,0.f,0.f};
    const float* Arow = A + srow * 1024 + skoff;
    float4 pa = *(const float4*)(Arow);
    float4 pb = *(const float4*)(Arow + 4);
    stage_store(As, 0, pa, pb, srow, skoff);
    for (int k0 = 0; k0 < 1024; k0 += 16) {
        int buf = (k0 >> 4) & 1;
        __syncthreads();
        if (k0 + 16 < 1024) {
            pa = *(const float4*)(Arow + k0 + 16);
            pb = *(const float4*)(Arow + k0 + 20);
            stage_store(As, buf ^ 1, pa, pb, srow, skoff);
        }
        const float* Ab = As + buf * 2048;
#pragma unroll
        for (int kk = 0; kk < 16; kk++) {
            float a0 = Ab[kk * 128 + b0r];
            float a1 = Ab[kk * 128 + b1r];
            float4 wv = *(const float4*)&WIs[(k0 + kk) * 16 + (tx << 2)];
            acc0[0] = fmaf(a0, wv.x, acc0[0]); acc0[1] = fmaf(a0, wv.y, acc0[1]);
            acc0[2] = fmaf(a0, wv.z, acc0[2]); acc0[3] = fmaf(a0, wv.w, acc0[3]);
            acc1[0] = fmaf(a1, wv.x, acc1[0]); acc1[1] = fmaf(a1, wv.y, acc1[1]);
            acc1[2] = fmaf(a1, wv.z, acc1[2]); acc1[3] = fmaf(a1, wv.w, acc1[3]);
        }
    }
    int d = (n0 >> 2) + tx;
    float4 bb = *(const float4*)&bI[n0 + (tx << 2)];
#pragma unroll
    for (int i = 0; i < 2; i++) {
        int b = (i == 0) ? b0r : b1r;
        float* acc = (i == 0) ? acc0 : acc1;
        float gi = acc[0] + bb.x;
        float gf = acc[1] + bb.y;
        float gg = acc[2] + bb.z;
        float go = acc[3] + bb.w;
        if (layer0) {
            float4 oh = *(const float4*)&g_ohI[(size_t)g_z[b] * 2048 + n0 + (tx << 2)];
            gi += oh.x; gf += oh.y; gg += oh.z; go += oh.w;
        }
        float ii = sigm(gi), ff = sigm(gf), g2 = tanhf(gg), oo = sigm(go);
        float c = ff * cs[b * 512 + d] + ii * g2;
        cs[b * 512 + d] = c;
        float hh = oo * tanhf(c);
        o1[b * ld1 + d] = hh;
        o2[b * ld2 + d] = hh;
    }
}

// ---------------- sq GEMM (blocks 128..143): 128 x 32 cols, K=512 -----------
__device__ void sq_block(const float* __restrict__ phis, float* As,
                         const float* __restrict__ phi_b) {
    int bs = blockIdx.x - 128;
    int n0s = bs * 32;
    int tid = threadIdx.x;
    int ty = tid >> 3;                  // 0..31
    int tx = tid & 7;                   // 0..7
    int srow = tid >> 1, skoff = (tid & 1) << 3;
    float acc[4][4];
#pragma unroll
    for (int i = 0; i < 4; i++)
#pragma unroll
        for (int j = 0; j < 4; j++) acc[i][j] = 0.f;
    const float* Arow = g_S1 + srow * 512 + skoff;
    float4 pa = *(const float4*)(Arow);
    float4 pb = *(const float4*)(Arow + 4);
    stage_store(As, 0, pa, pb, srow, skoff);
    for (int k0 = 0; k0 < 512; k0 += 16) {
        int buf = (k0 >> 4) & 1;
        __syncthreads();
        if (k0 + 16 < 512) {
            pa = *(const float4*)(Arow + k0 + 16);
            pb = *(const float4*)(Arow + k0 + 20);
            stage_store(As, buf ^ 1, pa, pb, srow, skoff);
        }
        const float* Ab = As + buf * 2048;
#pragma unroll
        for (int kk = 0; kk < 16; kk++) {
            float4 wv = *(const float4*)&phis[(k0 + kk) * 32 + (tx << 2)];
            float a0 = Ab[kk * 128 + ty];
            float a1 = Ab[kk * 128 + ty + 32];
            float a2 = Ab[kk * 128 + ty + 64];
            float a3 = Ab[kk * 128 + ty + 96];
            acc[0][0] = fmaf(a0, wv.x, acc[0][0]); acc[0][1] = fmaf(a0, wv.y, acc[0][1]);
            acc[0][2] = fmaf(a0, wv.z, acc[0][2]); acc[0][3] = fmaf(a0, wv.w, acc[0][3]);
            acc[1][0] = fmaf(a1, wv.x, acc[1][0]); acc[1][1] = fmaf(a1, wv.y, acc[1][1]);
            acc[1][2] = fmaf(a1, wv.z, acc[1][2]); acc[1][3] = fmaf(a1, wv.w, acc[1][3]);
            acc[2][0] = fmaf(a2, wv.x, acc[2][0]); acc[2][1] = fmaf(a2, wv.y, acc[2][1]);
            acc[2][2] = fmaf(a2, wv.z, acc[2][2]); acc[2][3] = fmaf(a2, wv.w, acc[2][3]);
            acc[3][0] = fmaf(a3, wv.x, acc[3][0]); acc[3][1] = fmaf(a3, wv.y, acc[3][1]);
            acc[3][2] = fmaf(a3, wv.z, acc[3][2]); acc[3][3] = fmaf(a3, wv.w, acc[3][3]);
        }
    }
    float4 pb4 = *(const float4*)&phi_b[n0s + (tx << 2)];
#pragma unroll
    for (int i = 0; i < 4; i++) {
        int b = ty + i * 32;
        float4 rr;
        rr.x = acc[i][0] + pb4.x; rr.y = acc[i][1] + pb4.y;
        rr.z = acc[i][2] + pb4.z; rr.w = acc[i][3] + pb4.w;
        *(float4*)&g_sq[b * 512 + n0s + (tx << 2)] = rr;
    }
}

// ---------------- attention: register-pipelined, per-warp online softmax ----
#define ATT_LOAD(V, ro) do {                                                  \
    const float* rp_ = hpw + (size_t)(ro) * 512;                              \
    _Pragma("unroll") for (int i_ = 0; i_ < 2; i_++)                          \
    _Pragma("unroll") for (int j_ = 0; j_ < 4; j_++)                          \
        V[i_][j_] = *(const float4*)(rp_ + i_ * 512 + j_ * 128 + (lane << 2));\
} while (0)

#define ATT_PROC(V) do {                                                      \
    float d0 = 0.f, d1 = 0.f;                                                 \
    _Pragma("unroll") for (int j_ = 0; j_ < 4; j_++) {                        \
        d0 = fmaf(qf[j_].x, V[0][j_].x, d0); d0 = fmaf(qf[j_].y, V[0][j_].y, d0); \
        d0 = fmaf(qf[j_].z, V[0][j_].z, d0); d0 = fmaf(qf[j_].w, V[0][j_].w, d0); \
        d1 = fmaf(qf[j_].x, V[1][j_].x, d1); d1 = fmaf(qf[j_].y, V[1][j_].y, d1); \
        d1 = fmaf(qf[j_].z, V[1][j_].z, d1); d1 = fmaf(qf[j_].w, V[1][j_].w, d1); } \
    _Pragma("unroll") for (int off_ = 16; off_ > 0; off_ >>= 1) {             \
        d0 += __shfl_xor_sync(0xffffffffu, d0, off_);                         \
        d1 += __shfl_xor_sync(0xffffffffu, d1, off_); }                       \
    float mn_ = fmaxf(m, fmaxf(d0, d1));                                      \
    float corr_ = __expf(m - mn_);                                            \
    float p0_ = __expf(d0 - mn_), p1_ = __expf(d1 - mn_);                     \
    s = s * corr_ + p0_ + p1_;                                                \
    _Pragma("unroll") for (int j_ = 0; j_ < 4; j_++) {                        \
        cacc[j_].x = fmaf(p0_, V[0][j_].x, fmaf(p1_, V[1][j_].x, cacc[j_].x * corr_)); \
        cacc[j_].y = fmaf(p0_, V[0][j_].y, fmaf(p1_, V[1][j_].y, cacc[j_].y * corr_)); \
        cacc[j_].z = fmaf(p0_, V[0][j_].z, fmaf(p1_, V[1][j_].z, cacc[j_].z * corr_)); \
        cacc[j_].w = fmaf(p0_, V[0][j_].w, fmaf(p1_, V[1][j_].w, cacc[j_].w * corr_)); } \
    m = mn_;                                                                  \
} while (0)

__device__ void attn_block(float* __restrict__ XAc) {
    __shared__ float sm_v[8][512];
    __shared__ float sm_ms[16];
    int b = blockIdx.x;
    int tid = threadIdx.x, lane = tid & 31, w = tid >> 5;
    const float* sqb = g_sq + b * 512;
    float4 qf[4];
#pragma unroll
    for (int j = 0; j < 4; j++)
        qf[j] = *(const float4*)(sqb + j * 128 + (lane << 2));
    const float* hpw = g_hp + (size_t)b * (R_ * HID_) + (size_t)w * 64 * 512;
    float m = -INFINITY, s = 0.f;
    float4 cacc[4];
#pragma unroll
    for (int j = 0; j < 4; j++) cacc[j] = make_float4(0.f, 0.f, 0.f, 0.f);
    float4 va[2][4], vb[2][4];
    ATT_LOAD(va, 0);
    for (int p = 0; p < 32; p += 2) {
        ATT_LOAD(vb, (p + 1) * 2);
        ATT_PROC(va);
        if (p + 2 < 32) ATT_LOAD(va, (p + 2) * 2);
        ATT_PROC(vb);
    }
#pragma unroll
    for (int j = 0; j < 4; j++)
        *(float4*)&sm_v[w][j * 128 + (lane << 2)] = cacc[j];
    if (lane == 0) { sm_ms[w] = m; sm_ms[8 + w] = s; }
    __syncthreads();
    float M = sm_ms[0];
#pragma unroll
    for (int i = 1; i < 8; i++) M = fmaxf(M, sm_ms[i]);
    float we[8]; float S = 0.f;
#pragma unroll
    for (int i = 0; i < 8; i++) { we[i] = __expf(sm_ms[i] - M); S = fmaf(sm_ms[8 + i], we[i], S); }
    float inv = 1.f / S;
    for (int c = tid; c < 512; c += NT) {
        float a = 0.f;
#pragma unroll
        for (int i = 0; i < 8; i++) a = fmaf(we[i], sm_v[i][c], a);
        XAc[b * 1024 + c] = a * inv;
    }
}

// ---------------- logits + sampler (bit-exact threefry path) ----------------
__device__ void logits_sample(int t, const float* __restrict__ out_b,
                              const int* __restrict__ y, float* __restrict__ out) {
    __shared__ float sl[4][64];
    __shared__ float sg2[64];
    int b = blockIdx.x;
    if (b < B_) {
        int tid = threadIdx.x, v = tid & 63, part = tid >> 6;
        const float* s1 = g_S1 + b * 512 + part * 128;
        const float* ot = g_outT + part * 128 * 64 + v;
        float a0 = 0.f, a1 = 0.f;
#pragma unroll 4
        for (int k = 0; k < 128; k += 2) {
            a0 = fmaf(s1[k],     ot[k * 64],       a0);
            a1 = fmaf(s1[k + 1], ot[(k + 1) * 64], a1);
        }
        sl[part][v] = a0 + a1;
        __syncthreads();
        uint2 kt = g_keys[t];
        uint32_t k1a, k1b;
        tf2x32(kt.x, kt.y, 0u, 0u, k1a, k1b);
        if (tid < 64) {
            float logit = sl[0][tid] + sl[1][tid] + sl[2][tid] + sl[3][tid] + out_b[tid];
            out[((size_t)b * T_ + t) * VOC_ + tid] = logit;
            uint32_t r0, r1;
            tf2x32(k1a, k1b, 0u, (uint32_t)(b * VOC_ + tid), r0, r1);
            float f = bits_to_unit(r0 ^ r1);
            float u2 = fmaxf(f, 1.17549435e-38f);
            sg2[tid] = logit + (-logf(-logf(u2)));
        }
        __syncthreads();
        if (tid < 32) {
            float v0 = sg2[tid], v1 = sg2[tid + 32];
            int i0 = tid;
            if (v1 > v0) { v0 = v1; i0 = tid + 32; }
#pragma unroll
            for (int off = 16; off > 0; off >>= 1) {
                float ov = __shfl_down_sync(0xffffffffu, v0, off);
                int   oi = __shfl_down_sync(0xffffffffu, i0, off);
                if (ov > v0 || (ov == v0 && oi < i0)) { v0 = ov; i0 = oi; }
            }
            if (tid == 0) {
                uint32_t k2a, k2b, r0, r1;
                tf2x32(kt.x, kt.y, 0u, 1u, k2a, k2b);
                tf2x32(k2a, k2b, 0u, (uint32_t)b, r0, r1);
                float f = fmaxf(bits_to_unit(r0 ^ r1), 0.0f);
                g_z[b] = (f < 0.1f) ? i0 : y[b * (T_ + 1) + t + 1];
            }
        }
        __syncthreads();
    }
}

// ============================================================================
__global__ void __launch_bounds__(NT)
aas_persistent(const float* __restrict__ h,
               const float* __restrict__ phi_w, const float* __restrict__ phi_b,
               const float* __restrict__ psi_w, const float* __restrict__ psi_b,
               const float* __restrict__ w_ih0, const float* __restrict__ w_hh0,
               const float* __restrict__ b_ih0, const float* __restrict__ b_hh0,
               const float* __restrict__ w_ih1, const float* __restrict__ w_hh1,
               const float* __restrict__ b_ih1, const float* __restrict__ b_hh1,
               const float* __restrict__ out_w, const float* __restrict__ out_b,
               const int* __restrict__ y, float* __restrict__ out) {
    extern __shared__ float sbuf[];
    int tid = threadIdx.x;
    int bx = blockIdx.x;

    phase_setup(psi_w, phi_b, w_ih0, b_ih0, b_hh0, b_ih1, b_hh1, out_w, y);
    gbar();

    // hp = h @ psi^T + psi_b  (uses sbuf scratch, then load resident tiles)
    gemm64(sbuf, h, g_psiT, g_hp, psi_b);

    if (bx < B_) {
        // resident gate weight tiles: WI0s/WI1s [1024][16], cols gate-interleaved
        int n0 = bx * 16, d0 = n0 >> 2;
        float* WI0s = sbuf;
        float* WI1s = sbuf + 16384;
        for (int i = tid; i < 16 * 1024; i += NT) {
            int c = i >> 10, k = i & 1023;
            int g = c & 3, d = d0 + (c >> 2);
            int oc = g * 512 + d;
            WI0s[k * 16 + c] = (k < 512) ? w_ih0[oc * 576 + 64 + k]
                                         : w_hh0[oc * 512 + (k - 512)];
            WI1s[k * 16 + c] = (k < 512) ? w_ih1[oc * 512 + k]
                                         : w_hh1[oc * 512 + (k - 512)];
        }
    } else if (bx < 144) {
        // resident phi tiles: phis [512][32]
        int n0s = (bx - 128) * 32;
        float* phis = sbuf;
        for (int i = tid; i < 32 * 512; i += NT) {
            int jj = i >> 9, k = i & 511;
            phis[k * 32 + jj] = phi_w[(n0s + jj) * 512 + k];
        }
    }
    gbar();

    float* AsG = sbuf + 32768;      // gates A-stage
    float* AsS = sbuf + 16384;      // sq A-stage
    int n0 = bx * 16;

    for (int t = 0; t < T_; t++) {
        float* XAc = g_XA[t & 1];
        float* XAn = g_XA[(t + 1) & 1];
        float* XBc = g_XB[t & 1];
        float* XBn = g_XB[(t + 1) & 1];
        // phase 1: attention -> c into XAc[:, :512]
        if (bx < B_) attn_block(XAc);
        gbar();
        // phase 2: gates0 + LSTM0 -> s0 into XBc[:, :512] and XAn[:, 512:]
        if (bx < B_)
            gemm_gates(XAc, sbuf, AsG, g_b0I, g_cs0, XBc, 1024, XAn + 512, 1024, n0, 1);
        gbar();
        // phase 3: gates1 + LSTM1 -> s1 into XBn[:, 512:] and S1
        if (bx < B_)
            gemm_gates(XBc, sbuf + 16384, AsG, g_b1I, g_cs1, XBn + 512, 1024, g_S1, 512, n0, 0);
        gbar();
        // phase 4: logits+sampler (blocks<128) and next-step sq (blocks 128..143)
        logits_sample(t, out_b, y, out);
        if (bx >= 128 && bx < 144) sq_block(sbuf, AsS, phi_b);
        gbar();
    }
}

extern "C" void kernel_launch(void* const* d_in, const int* in_sizes, int n_in,
                              void* d_out, int out_size) {
    const float* h     = (const float*)d_in[0];
    const float* phi_w = (const float*)d_in[1];
    const float* phi_b = (const float*)d_in[2];
    const float* psi_w = (const float*)d_in[3];
    const float* psi_b = (const float*)d_in[4];
    const float* w_ih0 = (const float*)d_in[5];
    const float* w_hh0 = (const float*)d_in[6];
    const float* b_ih0 = (const float*)d_in[7];
    const float* b_hh0 = (const float*)d_in[8];
    const float* w_ih1 = (const float*)d_in[9];
    const float* w_hh1 = (const float*)d_in[10];
    const float* b_ih1 = (const float*)d_in[11];
    const float* b_hh1 = (const float*)d_in[12];
    const float* out_w = (const float*)d_in[13];
    const float* out_b = (const float*)d_in[14];
    const int*   y     = (const int*)d_in[15];
    float* out = (float*)d_out;

    cudaFuncSetAttribute(aas_persistent,
                         cudaFuncAttributeMaxDynamicSharedMemorySize, SMEM_DYN);
    aas_persistent<<<NB, NT, SMEM_DYN>>>(h, phi_w, phi_b, psi_w, psi_b,
                                         w_ih0, w_hh0, b_ih0, b_hh0,
                                         w_ih1, w_hh1, b_ih1, b_hh1,
                                         out_w, out_b, y, out);
}